// round 12
// baseline (speedup 1.0000x reference)
#include <cuda_runtime.h>

#define C16  16
#define GH32 32
#define W512 512
#define HW   (512 * 512)

// All weights on the constant bank (R5/R8/R11-winning configuration).
#define OFF_W1 0        // [c][j]      16*32
#define OFF_W2 512      // [c][j]      16*32  (= g1w[:,16:] @ mw, folded)
#define OFF_G2 1024     // [gp][j][e]  8*32*2 (= g2w[2gp+e][j])
#define OFF_MW 1536     // [c][d]      16*16  (= mw[d][c])
#define OFF_B1 1792     // 32            (= g1b + g1w[:,16:] @ mb)
#define OFF_GB 1824     // 16            (g2b)
#define OFF_MB 1840     // 16            (mb)
#define NWC    1856

__constant__ __align__(16) float cwts[NWC];
__device__   __align__(16) float g_wbuf[NWC];

// Packed f32x2 ops (Blackwell sm_103a).
__device__ __forceinline__ float2 ffma2(float2 a, float2 b, float2 c) {
    float2 d;
    asm("fma.rn.f32x2 %0, %1, %2, %3;"
        : "=l"(reinterpret_cast<unsigned long long&>(d))
        : "l"(reinterpret_cast<unsigned long long&>(a)),
          "l"(reinterpret_cast<unsigned long long&>(b)),
          "l"(reinterpret_cast<unsigned long long&>(c)));
    return d;
}
__device__ __forceinline__ float2 fadd2(float2 a, float2 b) {
    float2 d;
    asm("add.rn.f32x2 %0, %1, %2;"
        : "=l"(reinterpret_cast<unsigned long long&>(d))
        : "l"(reinterpret_cast<unsigned long long&>(a)),
          "l"(reinterpret_cast<unsigned long long&>(b)));
    return d;
}
__device__ __forceinline__ float2 dup2(float v) { return make_float2(v, v); }
__device__ __forceinline__ float4 ldc4(int idx) {
    return *reinterpret_cast<const float4*>(&cwts[idx]);
}
__device__ __forceinline__ float2 ldc2(int idx) {
    return *reinterpret_cast<const float2*>(&cwts[idx]);
}

// ---- prep: fold weights into constant staging buffer ----
__global__ void prep_weights(const float* __restrict__ mw,  const float* __restrict__ mb,
                             const float* __restrict__ g1w, const float* __restrict__ g1b,
                             const float* __restrict__ g2w, const float* __restrict__ g2b)
{
    const int t = threadIdx.x;
    for (int i = t; i < C16 * GH32; i += 256) {
        int c = i >> 5, j = i & 31;
        g_wbuf[OFF_W1 + i] = g1w[j * (2 * C16) + c];
        float acc = 0.f;
        #pragma unroll
        for (int k = 0; k < C16; k++)
            acc += g1w[j * (2 * C16) + C16 + k] * mw[k * C16 + c];
        g_wbuf[OFF_W2 + i] = acc;
    }
    for (int i = t; i < 8 * GH32 * 2; i += 256) {
        int gp = i >> 6, r = i & 63, j = r >> 1, e = r & 1;
        g_wbuf[OFF_G2 + i] = g2w[(2 * gp + e) * GH32 + j];
    }
    if (t < 256) {
        int c = t >> 4, d = t & 15;
        g_wbuf[OFF_MW + t] = mw[d * C16 + c];
    }
    if (t < GH32) {
        float acc = g1b[t];
        #pragma unroll
        for (int k = 0; k < C16; k++)
            acc += g1w[t * (2 * C16) + C16 + k] * mb[k];
        g_wbuf[OFF_B1 + t] = acc;
    }
    if (t >= 32 && t < 32 + C16) g_wbuf[OFF_MB + t - 32] = mb[t - 32];
    if (t >= 64 && t < 64 + C16) g_wbuf[OFF_GB + t - 64] = g2b[t - 64];
}

// Identity: softmax over 8 identical affinities = 1/8 each, so
//   s      = mean of 8 rolls of x
//   agg    = mw @ s + mb
//   hidden = relu(W1 @ x + W2 @ s + b1')
//   out    = agg * sigmoid(g2w @ hidden + g2b)
//
// R10's occupancy (128 thr, 5 blocks/SM -> 20 warps/SM, 5/SMSP) with R11's
// cache geometry: each block is a 16x16 PIXEL TILE, halo ~37 KB, so
// 5 resident blocks (185 KB) fit the L1D carveout and 740 concurrent blocks
// (27 MB) sit far below L2 — R10's DRAM thrash was geometry, not registers.
// 4-chunk merged hidden keeps live regs ~100 <= the 102-reg cap.
__global__ __launch_bounds__(128, 5) void fused_graphaug_kernel(
    const float* __restrict__ x,
    float* __restrict__ out)
{
    const int t = threadIdx.x;

    // ---- 2D tile indexing: 16x16 px tile = 128 threads x 2 px ----
    // blockIdx: [b(2) | tileY(5, 32 tiles of 16 rows) | tileX(5, 32 tiles of 16 cols)]
    const int b     = blockIdx.x >> 10;
    const int rem   = blockIdx.x & 1023;
    const int tileY = rem >> 5;
    const int tileX = rem & 31;
    const int tx = t & 7;                        // col-pair 0..7
    const int ty = t >> 3;                       // row 0..15
    const int w0 = tileX * 16 + tx * 2;          // even column
    const int h  = tileY * 16 + ty;

    const float* xb    = x + (size_t)b * C16 * HW;
    const int    center = h * W512 + w0;

    // ---- s = mean of 8 rolls per channel (packed adds) ----
    float2 sv[C16];
    {
        constexpr int DY[8] = {-4, -4, -4, -3, -2, 2, 3, 4};
        constexpr int DX[8] = {-4, -1,  2,  4, -3, 3, -2, 4};
        int roff[8], cb[8];
        #pragma unroll
        for (int i = 0; i < 8; i++) {
            roff[i] = ((h - DY[i]) & (W512 - 1)) * W512;
            cb[i]   = (w0 - DX[i]) & (W512 - 1);
        }
        #pragma unroll
        for (int c = 0; c < C16; c++) {
            const float* xp = xb + c * HW;
            float2 acc = make_float2(0.f, 0.f);
            #pragma unroll
            for (int i = 0; i < 8; i++) {
                float2 v;
                if ((DX[i] & 1) == 0) {
                    // even dx: cb even <= 510 -> aligned contiguous float2
                    v = *reinterpret_cast<const float2*>(xp + roff[i] + cb[i]);
                } else {
                    v.x = __ldg(xp + roff[i] + cb[i]);
                    v.y = __ldg(xp + roff[i] + ((cb[i] + 1) & (W512 - 1)));
                }
                acc = fadd2(acc, v);
            }
            sv[c] = make_float2(acc.x * 0.125f, acc.y * 0.125f);
        }
    }

    // ---- gate accumulators: gacc[gp][px] packs outputs (2gp, 2gp+1) ----
    float2 gacc[8][2];
    #pragma unroll
    for (int gp = 0; gp < 8; gp++) {
        float2 gb = ldc2(OFF_GB + 2 * gp);
        gacc[gp][0] = gb; gacc[gp][1] = gb;
    }

    // ---- hidden in 4 chunks of 8 units, W1/W2 merged per c (hreg = 16 regs) ----
    #pragma unroll
    for (int jt = 0; jt < 4; jt++) {
        const int j0 = jt * 8;
        float2 hreg[4][2];                       // pairs (j0+2l, j0+2l+1) x 2 px
        #pragma unroll
        for (int jl = 0; jl < 4; jl++) {
            float2 bv = ldc2(OFF_B1 + j0 + 2 * jl);
            hreg[jl][0] = bv; hreg[jl][1] = bv;
        }
        #pragma unroll
        for (int c = 0; c < C16; c++) {
            float2 xc = *reinterpret_cast<const float2*>(xb + c * HW + center);
            float2 xd0 = dup2(xc.x), xd1 = dup2(xc.y);
            float2 sd0 = dup2(sv[c].x), sd1 = dup2(sv[c].y);
            float4 wa = ldc4(OFF_W1 + c * GH32 + j0);
            float4 wb = ldc4(OFF_W1 + c * GH32 + j0 + 4);
            float4 va = ldc4(OFF_W2 + c * GH32 + j0);
            float4 vb = ldc4(OFF_W2 + c * GH32 + j0 + 4);
            hreg[0][0] = ffma2(make_float2(wa.x, wa.y), xd0, hreg[0][0]);
            hreg[0][1] = ffma2(make_float2(wa.x, wa.y), xd1, hreg[0][1]);
            hreg[1][0] = ffma2(make_float2(wa.z, wa.w), xd0, hreg[1][0]);
            hreg[1][1] = ffma2(make_float2(wa.z, wa.w), xd1, hreg[1][1]);
            hreg[2][0] = ffma2(make_float2(wb.x, wb.y), xd0, hreg[2][0]);
            hreg[2][1] = ffma2(make_float2(wb.x, wb.y), xd1, hreg[2][1]);
            hreg[3][0] = ffma2(make_float2(wb.z, wb.w), xd0, hreg[3][0]);
            hreg[3][1] = ffma2(make_float2(wb.z, wb.w), xd1, hreg[3][1]);
            hreg[0][0] = ffma2(make_float2(va.x, va.y), sd0, hreg[0][0]);
            hreg[0][1] = ffma2(make_float2(va.x, va.y), sd1, hreg[0][1]);
            hreg[1][0] = ffma2(make_float2(va.z, va.w), sd0, hreg[1][0]);
            hreg[1][1] = ffma2(make_float2(va.z, va.w), sd1, hreg[1][1]);
            hreg[2][0] = ffma2(make_float2(vb.x, vb.y), sd0, hreg[2][0]);
            hreg[2][1] = ffma2(make_float2(vb.x, vb.y), sd1, hreg[2][1]);
            hreg[3][0] = ffma2(make_float2(vb.z, vb.w), sd0, hreg[3][0]);
            hreg[3][1] = ffma2(make_float2(vb.z, vb.w), sd1, hreg[3][1]);
        }
        // relu
        #pragma unroll
        for (int jl = 0; jl < 4; jl++) {
            hreg[jl][0].x = fmaxf(hreg[jl][0].x, 0.f);
            hreg[jl][0].y = fmaxf(hreg[jl][0].y, 0.f);
            hreg[jl][1].x = fmaxf(hreg[jl][1].x, 0.f);
            hreg[jl][1].y = fmaxf(hreg[jl][1].y, 0.f);
        }
        // gate accumulation
        #pragma unroll
        for (int jl = 0; jl < 4; jl++) {
            const int jg = j0 + 2 * jl;
            float2 ha0 = dup2(hreg[jl][0].x), hb0 = dup2(hreg[jl][0].y);
            float2 ha1 = dup2(hreg[jl][1].x), hb1 = dup2(hreg[jl][1].y);
            #pragma unroll
            for (int gp = 0; gp < 8; gp++) {
                float4 wq = ldc4(OFF_G2 + gp * 64 + jg * 2);
                gacc[gp][0] = ffma2(make_float2(wq.x, wq.y), ha0, gacc[gp][0]);
                gacc[gp][0] = ffma2(make_float2(wq.z, wq.w), hb0, gacc[gp][0]);
                gacc[gp][1] = ffma2(make_float2(wq.x, wq.y), ha1, gacc[gp][1]);
                gacc[gp][1] = ffma2(make_float2(wq.z, wq.w), hb1, gacc[gp][1]);
            }
        }
    }

    // ---- agg = mw @ s + mb, two d-pairs at a time, fused epilogue ----
    float* ob = out + (size_t)b * C16 * HW + center;
    #pragma unroll
    for (int dp = 0; dp < 8; dp += 2) {
        float2 mv0 = ldc2(OFF_MB + 2 * dp);
        float2 mv1 = ldc2(OFF_MB + 2 * dp + 2);
        float2 a00 = mv0, a01 = mv0;     // pair (2dp,2dp+1)   @ px0 / px1
        float2 a10 = mv1, a11 = mv1;     // pair (2dp+2,2dp+3) @ px0 / px1
        #pragma unroll
        for (int c = 0; c < C16; c++) {
            float2 sd0 = dup2(sv[c].x), sd1 = dup2(sv[c].y);
            float4 wq = ldc4(OFF_MW + c * C16 + dp * 2);
            a00 = ffma2(make_float2(wq.x, wq.y), sd0, a00);
            a01 = ffma2(make_float2(wq.x, wq.y), sd1, a01);
            a10 = ffma2(make_float2(wq.z, wq.w), sd0, a10);
            a11 = ffma2(make_float2(wq.z, wq.w), sd1, a11);
        }
        #pragma unroll
        for (int e = 0; e < 2; e++) {
            float2 v0 = e ? a10 : a00;           // px0: (d, d+1)
            float2 v1 = e ? a11 : a01;           // px1: (d, d+1)
            const int d0 = 2 * (dp + e);
            float g00 = 1.f / (1.f + __expf(-gacc[dp + e][0].x));
            float g01 = 1.f / (1.f + __expf(-gacc[dp + e][1].x));
            float g10 = 1.f / (1.f + __expf(-gacc[dp + e][0].y));
            float g11 = 1.f / (1.f + __expf(-gacc[dp + e][1].y));
            *reinterpret_cast<float2*>(ob + (size_t)d0 * HW) =
                make_float2(v0.x * g00, v1.x * g01);
            *reinterpret_cast<float2*>(ob + (size_t)(d0 + 1) * HW) =
                make_float2(v0.y * g10, v1.y * g11);
        }
    }
}

extern "C" void kernel_launch(void* const* d_in, const int* in_sizes, int n_in,
                              void* d_out, int out_size) {
    // metadata order: x, qw, qb, kw, kb, mw, mb, scaling, g1w, g1b, g2w, g2b
    const float* x   = (const float*)d_in[0];
    const float* mw  = (const float*)d_in[5];
    const float* mb  = (const float*)d_in[6];
    const float* g1w = (const float*)d_in[8];
    const float* g1b = (const float*)d_in[9];
    const float* g2w = (const float*)d_in[10];
    const float* g2b = (const float*)d_in[11];
    float* out = (float*)d_out;

    prep_weights<<<1, 256>>>(mw, mb, g1w, g1b, g2w, g2b);

    void* wsrc = nullptr;
    cudaGetSymbolAddress(&wsrc, g_wbuf);
    cudaMemcpyToSymbolAsync(cwts, wsrc, NWC * sizeof(float), 0,
                            cudaMemcpyDeviceToDevice, 0);

    // 4 batches x (32 y-tiles x 32 x-tiles) = 4096 blocks; 128 thr x 2 px = 16x16 tile
    fused_graphaug_kernel<<<4096, 128>>>(x, out);
}

// round 13
// speedup vs baseline: 1.5676x; 1.5676x over previous
#include <cuda_runtime.h>

#define C16  16
#define GH32 32
#define W512 512
#define HW   (512 * 512)

// Constant bank with PRE-DUPLICATED weights: every value stored as (w,w) so
// one LDC.128 yields two ready f32x2 broadcast operands for lane=(px0,px1)
// packing — zero register MOVs (the ~650 dup-MOVs/thread that throttled R8).
#define OFF_W1 0        // [c][j] dup: (c*32+j)*2       -> g1w[j][c]
#define OFF_W2 1024     // [c][j] dup                    -> (g1w[:,16:] @ mw)[j][c]
#define OFF_G2 2048     // [j][g] dup: (j*16+g)*2        -> g2w[g][j]
#define OFF_MW 3072     // [c][d] dup: (c*16+d)*2        -> mw[d][c]
#define OFF_B1 3584     // [j] dup                       -> g1b + g1w[:,16:] @ mb
#define OFF_GB 3648     // [g] dup                       -> g2b
#define OFF_MB 3680     // [d] dup                       -> mb
#define NWC    3712

__constant__ __align__(16) float cwts[NWC];
__device__   __align__(16) float g_wbuf[NWC];

// Packed f32x2 ops (Blackwell sm_103a).
__device__ __forceinline__ float2 ffma2(float2 a, float2 b, float2 c) {
    float2 d;
    asm("fma.rn.f32x2 %0, %1, %2, %3;"
        : "=l"(reinterpret_cast<unsigned long long&>(d))
        : "l"(reinterpret_cast<unsigned long long&>(a)),
          "l"(reinterpret_cast<unsigned long long&>(b)),
          "l"(reinterpret_cast<unsigned long long&>(c)));
    return d;
}
__device__ __forceinline__ float2 fadd2(float2 a, float2 b) {
    float2 d;
    asm("add.rn.f32x2 %0, %1, %2;"
        : "=l"(reinterpret_cast<unsigned long long&>(d))
        : "l"(reinterpret_cast<unsigned long long&>(a)),
          "l"(reinterpret_cast<unsigned long long&>(b)));
    return d;
}
__device__ __forceinline__ float4 ldc4(int idx) {
    return *reinterpret_cast<const float4*>(&cwts[idx]);
}
__device__ __forceinline__ float2 ldc2(int idx) {
    return *reinterpret_cast<const float2*>(&cwts[idx]);
}

// ---- prep: fold + DUPLICATE weights into constant staging buffer ----
__global__ void prep_weights(const float* __restrict__ mw,  const float* __restrict__ mb,
                             const float* __restrict__ g1w, const float* __restrict__ g1b,
                             const float* __restrict__ g2w, const float* __restrict__ g2b)
{
    const int t = threadIdx.x;
    // W1 / W2 : [c][j], duplicated
    for (int i = t; i < C16 * GH32; i += 256) {
        int c = i >> 5, j = i & 31;
        float w1 = g1w[j * (2 * C16) + c];
        g_wbuf[OFF_W1 + i * 2]     = w1;
        g_wbuf[OFF_W1 + i * 2 + 1] = w1;
        float acc = 0.f;
        #pragma unroll
        for (int k = 0; k < C16; k++)
            acc += g1w[j * (2 * C16) + C16 + k] * mw[k * C16 + c];
        g_wbuf[OFF_W2 + i * 2]     = acc;
        g_wbuf[OFF_W2 + i * 2 + 1] = acc;
    }
    // G2 : [j][g], duplicated
    for (int i = t; i < GH32 * C16; i += 256) {
        int j = i >> 4, g = i & 15;
        float v = g2w[g * GH32 + j];
        g_wbuf[OFF_G2 + i * 2]     = v;
        g_wbuf[OFF_G2 + i * 2 + 1] = v;
    }
    // MW : [c][d], duplicated
    if (t < 256) {
        int c = t >> 4, d = t & 15;
        float v = mw[d * C16 + c];
        g_wbuf[OFF_MW + t * 2]     = v;
        g_wbuf[OFF_MW + t * 2 + 1] = v;
    }
    // b1' folded, duplicated
    if (t < GH32) {
        float acc = g1b[t];
        #pragma unroll
        for (int k = 0; k < C16; k++)
            acc += g1w[t * (2 * C16) + C16 + k] * mb[k];
        g_wbuf[OFF_B1 + 2 * t]     = acc;
        g_wbuf[OFF_B1 + 2 * t + 1] = acc;
    }
    if (t >= 32 && t < 32 + C16) {
        int d = t - 32;
        g_wbuf[OFF_MB + 2 * d] = mb[d];  g_wbuf[OFF_MB + 2 * d + 1] = mb[d];
    }
    if (t >= 64 && t < 64 + C16) {
        int g = t - 64;
        g_wbuf[OFF_GB + 2 * g] = g2b[g]; g_wbuf[OFF_GB + 2 * g + 1] = g2b[g];
    }
}

// Identity: softmax over 8 identical affinities = 1/8 each, so
//   s      = mean of 8 rolls of x
//   agg    = mw @ s + mb
//   hidden = relu(W1 @ x + W2 @ s + b1')
//   out    = agg * sigmoid(g2w @ hidden + g2b)
//
// R8 shape (2 px/thread, 256 thr, occ-2, 128 regs, zero smem) with lanes =
// (px0,px1): activations are naturally-packed f32x2 (loads, sv, hreg, gacc,
// stores all mov-free) and weights arrive pre-duplicated from the constant
// bank. Arithmetic identical to R8; ~650 dependent MOVs/thread removed.
__global__ __launch_bounds__(256, 2) void fused_graphaug_kernel(
    const float* __restrict__ x,
    float* __restrict__ out)
{
    const int t = threadIdx.x;

    // ---- Pixel-pair indexing (2 horizontally-adjacent pixels per thread) ----
    const int tidg = blockIdx.x * 256 + t;
    const int p0   = tidg * 2;
    const int w0   = p0 & (W512 - 1);            // even column
    const int h    = (p0 >> 9) & (W512 - 1);
    const int b    = p0 >> 18;

    const float* xb    = x + (size_t)b * C16 * HW;
    const int    center = h * W512 + w0;

    // ---- s = mean of 8 rolls per channel, lanes (px0,px1) ----
    float2 sv[C16];
    {
        constexpr int DY[8] = {-4, -4, -4, -3, -2, 2, 3, 4};
        constexpr int DX[8] = {-4, -1,  2,  4, -3, 3, -2, 4};
        int roff[8], cb[8];
        #pragma unroll
        for (int i = 0; i < 8; i++) {
            roff[i] = ((h - DY[i]) & (W512 - 1)) * W512;
            cb[i]   = (w0 - DX[i]) & (W512 - 1);
        }
        #pragma unroll
        for (int c = 0; c < C16; c++) {
            const float* xp = xb + c * HW;
            float2 acc = make_float2(0.f, 0.f);
            #pragma unroll
            for (int i = 0; i < 8; i++) {
                float2 v;
                if ((DX[i] & 1) == 0) {
                    // even dx: cb even <= 510 -> aligned contiguous float2
                    v = *reinterpret_cast<const float2*>(xp + roff[i] + cb[i]);
                } else {
                    v.x = __ldg(xp + roff[i] + cb[i]);
                    v.y = __ldg(xp + roff[i] + ((cb[i] + 1) & (W512 - 1)));
                }
                acc = fadd2(acc, v);
            }
            sv[c] = make_float2(acc.x * 0.125f, acc.y * 0.125f);
        }
    }

    // ---- gate accumulators: gacc[g] = (gatepre_g@px0, gatepre_g@px1) ----
    float2 gacc[C16];
    #pragma unroll
    for (int g = 0; g < C16; g++)
        gacc[g] = ldc2(OFF_GB + 2 * g);

    // ---- hidden in 2 chunks of 16 units; hreg[j] = (h_j@px0, h_j@px1) ----
    #pragma unroll
    for (int jt = 0; jt < 2; jt++) {
        const int j0 = jt * 16;
        float2 hreg[16];
        #pragma unroll
        for (int j = 0; j < 16; j++)
            hreg[j] = ldc2(OFF_B1 + (j0 + j) * 2);

        // W1 @ x : weights pre-dup'd, xc is the natural (px0,px1) pair
        #pragma unroll
        for (int c = 0; c < C16; c++) {
            float2 xc = *reinterpret_cast<const float2*>(xb + c * HW + center);
            #pragma unroll
            for (int q = 0; q < 8; q++) {        // 8 ldc4 cover 16 dup'd units
                float4 wq = ldc4(OFF_W1 + (c * GH32 + j0 + 2 * q) * 2);
                hreg[2*q]   = ffma2(make_float2(wq.x, wq.y), xc, hreg[2*q]);
                hreg[2*q+1] = ffma2(make_float2(wq.z, wq.w), xc, hreg[2*q+1]);
            }
        }
        // W2 @ s
        #pragma unroll
        for (int c = 0; c < C16; c++) {
            float2 sc = sv[c];
            #pragma unroll
            for (int q = 0; q < 8; q++) {
                float4 wq = ldc4(OFF_W2 + (c * GH32 + j0 + 2 * q) * 2);
                hreg[2*q]   = ffma2(make_float2(wq.x, wq.y), sc, hreg[2*q]);
                hreg[2*q+1] = ffma2(make_float2(wq.z, wq.w), sc, hreg[2*q+1]);
            }
        }
        // relu (scalar fmax on both lanes)
        #pragma unroll
        for (int j = 0; j < 16; j++) {
            hreg[j].x = fmaxf(hreg[j].x, 0.f);
            hreg[j].y = fmaxf(hreg[j].y, 0.f);
        }
        // gate accumulation: gacc[g] += dup(G2[g][j]) * hreg[j]
        #pragma unroll
        for (int j = 0; j < 16; j++) {
            const int jg = j0 + j;
            float2 hv = hreg[j];
            #pragma unroll
            for (int q = 0; q < 8; q++) {        // 8 ldc4 cover 16 g
                float4 wq = ldc4(OFF_G2 + (jg * C16 + 2 * q) * 2);
                gacc[2*q]   = ffma2(make_float2(wq.x, wq.y), hv, gacc[2*q]);
                gacc[2*q+1] = ffma2(make_float2(wq.z, wq.w), hv, gacc[2*q+1]);
            }
        }
    }

    // ---- agg = mw @ s + mb : agg[d] = (agg_d@px0, agg_d@px1) ----
    float2 agg[C16];
    #pragma unroll
    for (int d = 0; d < C16; d++)
        agg[d] = ldc2(OFF_MB + 2 * d);
    #pragma unroll
    for (int c = 0; c < C16; c++) {
        float2 sc = sv[c];
        #pragma unroll
        for (int q = 0; q < 8; q++) {            // 8 ldc4 cover 16 d
            float4 wq = ldc4(OFF_MW + (c * C16 + 2 * q) * 2);
            agg[2*q]   = ffma2(make_float2(wq.x, wq.y), sc, agg[2*q]);
            agg[2*q+1] = ffma2(make_float2(wq.z, wq.w), sc, agg[2*q+1]);
        }
    }

    // ---- epilogue: out = agg * sigmoid(gacc); (px0,px1) store is one STG.64 ----
    float* ob = out + (size_t)b * C16 * HW + center;
    #pragma unroll
    for (int d = 0; d < C16; d++) {
        float g0 = 1.f / (1.f + __expf(-gacc[d].x));
        float g1 = 1.f / (1.f + __expf(-gacc[d].y));
        *reinterpret_cast<float2*>(ob + (size_t)d * HW) =
            make_float2(agg[d].x * g0, agg[d].y * g1);
    }
}

extern "C" void kernel_launch(void* const* d_in, const int* in_sizes, int n_in,
                              void* d_out, int out_size) {
    // metadata order: x, qw, qb, kw, kb, mw, mb, scaling, g1w, g1b, g2w, g2b
    const float* x   = (const float*)d_in[0];
    const float* mw  = (const float*)d_in[5];
    const float* mb  = (const float*)d_in[6];
    const float* g1w = (const float*)d_in[8];
    const float* g1b = (const float*)d_in[9];
    const float* g2w = (const float*)d_in[10];
    const float* g2b = (const float*)d_in[11];
    float* out = (float*)d_out;

    prep_weights<<<1, 256>>>(mw, mb, g1w, g1b, g2w, g2b);

    void* wsrc = nullptr;
    cudaGetSymbolAddress(&wsrc, g_wbuf);
    cudaMemcpyToSymbolAsync(cwts, wsrc, NWC * sizeof(float), 0,
                            cudaMemcpyDeviceToDevice, 0);

    // 1,048,576 px -> 524,288 horizontal pairs -> 2048 blocks x 256 threads
    fused_graphaug_kernel<<<2048, 256>>>(x, out);
}